// round 3
// baseline (speedup 1.0000x reference)
#include <cuda_runtime.h>
#include <math.h>

// ---------------- problem constants ----------------
static const int Bn  = 8;
static const int Ssz = 1024;
static const int INd = 128;
static const int Ech = 512;
static const int Hh  = 8;
static const int FFd = 2048;
static const int Ld  = 4;
static const int HDd = 64;
static const int ROWS = Bn * Ssz;       // 8192
#define EPSV 1e-5f

// ---------------- device scratch (no allocation allowed) ----------------
__device__ float g_x   [8192 * 512];
__device__ float g_qkv [8192 * 1536];
__device__ float g_scores[67108864ull];     // [B,H,S,S] = 256 MB
__device__ float g_w   [8388608ull];        // [B,S,S]  avg_w / w
__device__ float g_db  [8388608ull];        // [B,S,S]  dist bias
__device__ float g_attn[8192 * 512];
__device__ float g_ff1 [8192 * 2048];
__device__ float g_ff2 [8192 * 512];
__device__ float g_mu  [512];
__device__ float g_rv  [512];

// ---------------- reductions ----------------
__device__ __forceinline__ float blockReduce(float v, float* red, int isMax) {
    #pragma unroll
    for (int o = 16; o; o >>= 1) {
        float u = __shfl_xor_sync(0xffffffffu, v, o);
        v = isMax ? fmaxf(v, u) : (v + u);
    }
    int lane = threadIdx.x & 31, wid = threadIdx.x >> 5;
    int nw = blockDim.x >> 5;
    __syncthreads();                 // protect red from previous use
    if (lane == 0) red[wid] = v;
    __syncthreads();
    v = (threadIdx.x < nw) ? red[threadIdx.x] : (isMax ? -INFINITY : 0.0f);
    if (wid == 0) {
        #pragma unroll
        for (int o = 16; o; o >>= 1) {
            float u = __shfl_xor_sync(0xffffffffu, v, o);
            v = isMax ? fmaxf(v, u) : (v + u);
        }
        if (lane == 0) red[0] = v;
    }
    __syncthreads();
    return red[0];
}

// ---------------- generic 128x128x8 SGEMM ----------------
// C[m,n] = alpha * sum_k A[m,k] * (BT ? B[n,k] : B[k,n])  (+bias[n]) (relu)
// batched: z -> (bb = z/batchH, hh = z%batchH); pointer offsets sXb*bb + sXh*hh.
template<bool BT, bool RELU, bool BIAS>
__global__ __launch_bounds__(256, 2)
void gemm_k(const float* __restrict__ A, const float* __restrict__ B,
            const float* __restrict__ bias, float* __restrict__ C,
            int M, int N, int K, int lda, int ldb, int ldc,
            int batchH,
            long long sAb, long long sAh,
            long long sBb, long long sBh,
            long long sCb, long long sCh,
            float alpha)
{
    __shared__ float As[2][8][128];
    __shared__ float Bs[2][8][128];

    int z = blockIdx.z;
    int bb = z / batchH, hh = z - bb * batchH;
    A += bb * sAb + hh * sAh;
    B += bb * sBb + hh * sBh;
    C += bb * sCb + hh * sCh;

    int m0 = blockIdx.y * 128, n0 = blockIdx.x * 128;
    int t = threadIdx.x;

    int arow = t >> 1, acol = (t & 1) * 4;
    int brow, bcol;
    if (BT) { brow = t >> 1; bcol = (t & 1) * 4; }
    else    { brow = t >> 5; bcol = (t & 31) * 4; }

    const float* Ag = A + (size_t)(m0 + arow) * lda + acol;
    const float* Bg = BT ? (B + (size_t)(n0 + brow) * ldb + bcol)
                         : (B + (size_t)brow * ldb + n0 + bcol);

    // prologue: tile 0 -> buffer 0
    {
        float4 av = *(const float4*)Ag;
        float4 bv = *(const float4*)Bg;
        As[0][acol + 0][arow] = av.x; As[0][acol + 1][arow] = av.y;
        As[0][acol + 2][arow] = av.z; As[0][acol + 3][arow] = av.w;
        if (BT) {
            Bs[0][bcol + 0][brow] = bv.x; Bs[0][bcol + 1][brow] = bv.y;
            Bs[0][bcol + 2][brow] = bv.z; Bs[0][bcol + 3][brow] = bv.w;
        } else {
            *(float4*)&Bs[0][brow][bcol] = bv;
        }
    }
    __syncthreads();

    int tm = (t >> 4) * 8, tn = (t & 15) * 8;
    float acc[8][8];
    #pragma unroll
    for (int i = 0; i < 8; i++)
        #pragma unroll
        for (int j = 0; j < 8; j++) acc[i][j] = 0.0f;

    int nk = K >> 3;
    for (int kt = 0; kt < nk; ++kt) {
        int buf = kt & 1;
        float4 an, bn;
        if (kt + 1 < nk) {
            an = *(const float4*)(Ag + (kt + 1) * 8);
            bn = BT ? *(const float4*)(Bg + (kt + 1) * 8)
                    : *(const float4*)(Bg + (size_t)(kt + 1) * 8 * ldb);
        }
        #pragma unroll
        for (int k = 0; k < 8; k++) {
            float a[8], b[8];
            *(float4*)&a[0] = *(const float4*)&As[buf][k][tm];
            *(float4*)&a[4] = *(const float4*)&As[buf][k][tm + 4];
            *(float4*)&b[0] = *(const float4*)&Bs[buf][k][tn];
            *(float4*)&b[4] = *(const float4*)&Bs[buf][k][tn + 4];
            #pragma unroll
            for (int i = 0; i < 8; i++)
                #pragma unroll
                for (int j = 0; j < 8; j++)
                    acc[i][j] = fmaf(a[i], b[j], acc[i][j]);
        }
        if (kt + 1 < nk) {
            int nb = buf ^ 1;
            As[nb][acol + 0][arow] = an.x; As[nb][acol + 1][arow] = an.y;
            As[nb][acol + 2][arow] = an.z; As[nb][acol + 3][arow] = an.w;
            if (BT) {
                Bs[nb][bcol + 0][brow] = bn.x; Bs[nb][bcol + 1][brow] = bn.y;
                Bs[nb][bcol + 2][brow] = bn.z; Bs[nb][bcol + 3][brow] = bn.w;
            } else {
                *(float4*)&Bs[nb][brow][bcol] = bn;
            }
        }
        __syncthreads();
    }

    float bq[8];
    if (BIAS) {
        #pragma unroll
        for (int j = 0; j < 8; j++) bq[j] = bias[n0 + tn + j];
    }
    #pragma unroll
    for (int i = 0; i < 8; i++) {
        float out[8];
        #pragma unroll
        for (int j = 0; j < 8; j++) {
            float v = alpha * acc[i][j];
            if (BIAS) v += bq[j];
            if (RELU) v = fmaxf(v, 0.0f);
            out[j] = v;
        }
        float* cp = C + (size_t)(m0 + tm + i) * ldc + n0 + tn;
        *(float4*)cp       = *(float4*)&out[0];
        *(float4*)(cp + 4) = *(float4*)&out[4];
    }
}

// ---------------- BatchNorm stats: per-channel mean / rsqrt(var+eps) ----------------
__global__ void bn_stats_k(const float* __restrict__ x, float* __restrict__ mu,
                           float* __restrict__ rv)
{
    __shared__ float red[32];
    int c = blockIdx.x;
    float s = 0.f, ss = 0.f;
    for (int r = threadIdx.x; r < ROWS; r += blockDim.x) {
        float v = x[(size_t)r * Ech + c];
        s += v; ss += v * v;
    }
    s  = blockReduce(s,  red, 0);
    ss = blockReduce(ss, red, 0);
    if (threadIdx.x == 0) {
        float m = s / (float)ROWS;
        float var = ss / (float)ROWS - m * m;
        mu[c] = m;
        rv[c] = rsqrtf(var + EPSV);
    }
}

// ---------------- BN apply + sinusoidal PE ----------------
__global__ void bn_pe_k(float* __restrict__ x, const float* __restrict__ mu,
                        const float* __restrict__ rv, const float* __restrict__ g,
                        const float* __restrict__ b)
{
    size_t idx = (size_t)blockIdx.x * blockDim.x + threadIdx.x;
    if (idx >= (size_t)ROWS * Ech) return;
    int c = (int)(idx & (Ech - 1));
    int row = (int)(idx >> 9);
    int s = row & (Ssz - 1);
    int i2 = c & ~1;
    float dt = expf(-logf(10000.0f) * (float)i2 / (float)Ech);
    float ang = (float)s * dt;
    float pe = (c & 1) ? cosf(ang) : sinf(ang);
    x[idx] = (x[idx] - mu[c]) * rv[c] * g[c] + b[c] + pe;
}

// ---------------- distance bias: exp(scale*(1 - d/rowmax)) ----------------
__global__ void distb_k(const float* __restrict__ dist, const float* __restrict__ scale_p,
                        float* __restrict__ out)
{
    __shared__ float red[32];
    size_t bq = blockIdx.x;
    const float* row = dist + bq * Ssz;
    float m = -INFINITY;
    for (int i = threadIdx.x; i < Ssz; i += blockDim.x) m = fmaxf(m, row[i]);
    m = blockReduce(m, red, 1);
    float sc = *scale_p;
    float invm = 1.0f / m;
    for (int i = threadIdx.x; i < Ssz; i += blockDim.x)
        out[bq * Ssz + i] = expf(sc * (1.0f - row[i] * invm));
}

// ---------------- per-row: softmax over 8 heads, average, * dist_bias, renorm ----------------
__global__ void softmax_avg_k(const float* __restrict__ scores,
                              const float* __restrict__ db,
                              float* __restrict__ wout)
{
    __shared__ float avg[1024];
    __shared__ float tmp[1024];
    __shared__ float red[32];
    int bq = blockIdx.x;
    int b = bq >> 10, q = bq & 1023;
    int t = threadIdx.x;

    for (int i = t; i < Ssz; i += blockDim.x) avg[i] = 0.0f;
    __syncthreads();

    for (int h = 0; h < Hh; h++) {
        const float* row = scores + (((size_t)(b * Hh + h) * Ssz + q) * Ssz);
        float m = -INFINITY;
        for (int i = t; i < Ssz; i += blockDim.x) m = fmaxf(m, row[i]);
        m = blockReduce(m, red, 1);
        float s = 0.0f;
        for (int i = t; i < Ssz; i += blockDim.x) {
            float e = expf(row[i] - m);
            tmp[i] = e;
            s += e;
        }
        s = blockReduce(s, red, 0);
        float inv = 1.0f / ((float)Hh * s);
        for (int i = t; i < Ssz; i += blockDim.x) avg[i] += tmp[i] * inv;
    }

    const float* dbr = db + (size_t)bq * Ssz;
    float s = 0.0f;
    for (int i = t; i < Ssz; i += blockDim.x) {
        float v = avg[i] * dbr[i];
        tmp[i] = v;
        s += v;
    }
    s = blockReduce(s, red, 0);
    float inv = 1.0f / s;
    for (int i = t; i < Ssz; i += blockDim.x)
        wout[(size_t)bq * Ssz + i] = tmp[i] * inv;
}

// ---------------- residual + LayerNorm (row = 512) ----------------
__global__ void add_ln_k(const float* __restrict__ xin, const float* __restrict__ res,
                         const float* __restrict__ g, const float* __restrict__ b,
                         float* __restrict__ xout)
{
    __shared__ float red[32];
    int row = blockIdx.x;
    int t = threadIdx.x;                       // 128 threads * 4 = 512
    const float4* x4 = (const float4*)(xin + (size_t)row * Ech);
    const float4* r4 = (const float4*)(res + (size_t)row * Ech);
    float4 a = x4[t], c = r4[t];
    float y0 = a.x + c.x, y1 = a.y + c.y, y2 = a.z + c.z, y3 = a.w + c.w;
    float s  = y0 + y1 + y2 + y3;
    float ss = y0 * y0 + y1 * y1 + y2 * y2 + y3 * y3;
    s  = blockReduce(s,  red, 0);
    ss = blockReduce(ss, red, 0);
    float mean = s / (float)Ech;
    float var  = ss / (float)Ech - mean * mean;
    float rstd = rsqrtf(var + EPSV);
    const float4* g4 = (const float4*)g;
    const float4* b4 = (const float4*)b;
    float4 gg = g4[t], bb = b4[t];
    float4 o;
    o.x = (y0 - mean) * rstd * gg.x + bb.x;
    o.y = (y1 - mean) * rstd * gg.y + bb.y;
    o.z = (y2 - mean) * rstd * gg.z + bb.z;
    o.w = (y3 - mean) * rstd * gg.w + bb.w;
    ((float4*)(xout + (size_t)row * Ech))[t] = o;
}

// ---------------- host orchestration ----------------
extern "C" void kernel_launch(void* const* d_in, const int* in_sizes, int n_in,
                              void* d_out, int out_size)
{
    const float* src        = (const float*)d_in[0];
    const float* distances  = (const float*)d_in[1];
    const float* proj_w     = (const float*)d_in[2];
    const float* proj_b     = (const float*)d_in[3];
    const float* bn_g       = (const float*)d_in[4];
    const float* bn_b       = (const float*)d_in[5];
    const float* in_proj_w  = (const float*)d_in[6];
    const float* in_proj_b  = (const float*)d_in[7];
    const float* dist_scale = (const float*)d_in[8];
    const float* lin1_w     = (const float*)d_in[9];
    const float* lin1_b     = (const float*)d_in[10];
    const float* lin2_w     = (const float*)d_in[11];
    const float* lin2_b     = (const float*)d_in[12];
    const float* n1_g       = (const float*)d_in[13];
    const float* n1_b       = (const float*)d_in[14];
    const float* n2_g       = (const float*)d_in[15];
    const float* n2_b       = (const float*)d_in[16];
    float* out = (float*)d_out;

    float *x, *qkv, *scores, *w, *db, *attn, *ff1, *ff2, *mu, *rv;
    cudaGetSymbolAddress((void**)&x,      g_x);
    cudaGetSymbolAddress((void**)&qkv,    g_qkv);
    cudaGetSymbolAddress((void**)&scores, g_scores);
    cudaGetSymbolAddress((void**)&w,      g_w);
    cudaGetSymbolAddress((void**)&db,     g_db);
    cudaGetSymbolAddress((void**)&attn,   g_attn);
    cudaGetSymbolAddress((void**)&ff1,    g_ff1);
    cudaGetSymbolAddress((void**)&ff2,    g_ff2);
    cudaGetSymbolAddress((void**)&mu,     g_mu);
    cudaGetSymbolAddress((void**)&rv,     g_rv);

    const long long SQKV = (long long)Ssz * 3 * Ech;     // 1572864
    const long long SHSS = (long long)Hh * Ssz * Ssz;    // 8388608
    const long long SSS  = (long long)Ssz * Ssz;         // 1048576
    const long long SXE  = (long long)Ssz * Ech;         // 524288

    // 1. input projection: x = src @ proj_w^T + proj_b
    gemm_k<true, false, true><<<dim3(Ech / 128, ROWS / 128, 1), 256>>>(
        src, proj_w, proj_b, x, ROWS, Ech, INd, INd, INd, Ech,
        1, 0, 0, 0, 0, 0, 0, 1.0f);

    // 2. BatchNorm stats + apply + PE
    bn_stats_k<<<Ech, 256>>>(x, mu, rv);
    bn_pe_k<<<(ROWS * Ech + 255) / 256, 256>>>(x, mu, rv, bn_g, bn_b);

    // 3. distance bias (layer-invariant)
    distb_k<<<ROWS, 256>>>(distances, dist_scale, db);

    const float scale = 0.125f;  // 1/sqrt(64)

    for (int l = 0; l < Ld; ++l) {
        // qkv = x @ in_proj_w^T + b
        gemm_k<true, false, true><<<dim3(3 * Ech / 128, ROWS / 128, 1), 256>>>(
            x, in_proj_w, in_proj_b, qkv, ROWS, 3 * Ech, Ech, Ech, Ech, 3 * Ech,
            1, 0, 0, 0, 0, 0, 0, 1.0f);

        // scores[b,h] = scale * q[b,h] @ k[b,h]^T   (64 batches)
        gemm_k<true, false, false><<<dim3(Ssz / 128, Ssz / 128, Bn * Hh), 256>>>(
            qkv, qkv + Ech, nullptr, scores, Ssz, Ssz, HDd,
            3 * Ech, 3 * Ech, Ssz,
            Hh, SQKV, HDd, SQKV, HDd, SHSS, SSS, scale);

        // per-row softmax over heads, average, *dist_bias, renormalize
        softmax_avg_k<<<ROWS, 256>>>(scores, db, w);

        // attn_out = w @ x   (8 batches)
        gemm_k<false, false, false><<<dim3(Ech / 128, Ssz / 128, Bn), 256>>>(
            w, x, nullptr, attn, Ssz, Ech, Ssz, Ssz, Ech, Ech,
            1, SSS, 0, SXE, 0, SXE, 0, 1.0f);

        // x = LN(x + attn_out)
        add_ln_k<<<ROWS, 128>>>(x, attn, n1_g, n1_b, x);

        // ff1 = relu(x @ lin1_w^T + b)
        gemm_k<true, true, true><<<dim3(FFd / 128, ROWS / 128, 1), 256>>>(
            x, lin1_w, lin1_b, ff1, ROWS, FFd, Ech, Ech, Ech, FFd,
            1, 0, 0, 0, 0, 0, 0, 1.0f);

        // ff2 = ff1 @ lin2_w^T + b
        gemm_k<true, false, true><<<dim3(Ech / 128, ROWS / 128, 1), 256>>>(
            ff1, lin2_w, lin2_b, ff2, ROWS, Ech, FFd, FFd, FFd, Ech,
            1, 0, 0, 0, 0, 0, 0, 1.0f);

        // x = LN(x + ff2); last layer writes final output
        add_ln_k<<<ROWS, 128>>>(x, ff2, n2_g, n2_b, (l == Ld - 1) ? out : x);
    }
}

// round 4
// speedup vs baseline: 1.6142x; 1.6142x over previous
#include <cuda_runtime.h>
#include <math.h>

// ---------------- problem constants ----------------
static const int Bn  = 8;
static const int Ssz = 1024;
static const int INd = 128;
static const int Ech = 512;
static const int Hh  = 8;
static const int FFd = 2048;
static const int Ld  = 4;
static const int HDd = 64;
static const int ROWS = Bn * Ssz;       // 8192
#define EPSV 1e-5f

// ---------------- device scratch (no allocation allowed) ----------------
__device__ float g_x   [8192 * 512];
__device__ float g_qkv [8192 * 1536];
__device__ float g_scores[67108864ull];     // [B,H,S,S] = 256 MB
__device__ float g_w   [8388608ull];        // [B,S,S]  avg_w / w
__device__ float g_db  [8388608ull];        // [B,S,S]  dist bias
__device__ float g_attn[8192 * 512];
__device__ float g_ff1 [8192 * 2048];
__device__ float g_ff2 [8192 * 512];
__device__ float g_mu  [512];
__device__ float g_rv  [512];

// ---------------- reductions ----------------
__device__ __forceinline__ float blockReduce(float v, float* red, int isMax) {
    #pragma unroll
    for (int o = 16; o; o >>= 1) {
        float u = __shfl_xor_sync(0xffffffffu, v, o);
        v = isMax ? fmaxf(v, u) : (v + u);
    }
    int lane = threadIdx.x & 31, wid = threadIdx.x >> 5;
    int nw = blockDim.x >> 5;
    __syncthreads();                 // protect red from previous use
    if (lane == 0) red[wid] = v;
    __syncthreads();
    v = (threadIdx.x < nw) ? red[threadIdx.x] : (isMax ? -INFINITY : 0.0f);
    if (wid == 0) {
        #pragma unroll
        for (int o = 16; o; o >>= 1) {
            float u = __shfl_xor_sync(0xffffffffu, v, o);
            v = isMax ? fmaxf(v, u) : (v + u);
        }
        if (lane == 0) red[0] = v;
    }
    __syncthreads();
    return red[0];
}

// ---------------- generic 128x128x8 SGEMM ----------------
// C[m,n] = alpha * sum_k A[m,k] * (BT ? B[n,k] : B[k,n])  (+bias[n]) (relu)
// batched: z -> (bb = z/batchH, hh = z%batchH); pointer offsets sXb*bb + sXh*hh.
template<bool BT, bool RELU, bool BIAS>
__global__ __launch_bounds__(256, 2)
void gemm_k(const float* __restrict__ A, const float* __restrict__ B,
            const float* __restrict__ bias, float* __restrict__ C,
            int M, int N, int K, int lda, int ldb, int ldc,
            int batchH,
            long long sAb, long long sAh,
            long long sBb, long long sBh,
            long long sCb, long long sCh,
            float alpha)
{
    __shared__ float As[2][8][128];
    __shared__ float Bs[2][8][128];

    int z = blockIdx.z;
    int bb = z / batchH, hh = z - bb * batchH;
    A += bb * sAb + hh * sAh;
    B += bb * sBb + hh * sBh;
    C += bb * sCb + hh * sCh;

    int m0 = blockIdx.y * 128, n0 = blockIdx.x * 128;
    int t = threadIdx.x;

    int arow = t >> 1, acol = (t & 1) * 4;
    int brow, bcol;
    if (BT) { brow = t >> 1; bcol = (t & 1) * 4; }
    else    { brow = t >> 5; bcol = (t & 31) * 4; }

    const float* Ag = A + (size_t)(m0 + arow) * lda + acol;
    const float* Bg = BT ? (B + (size_t)(n0 + brow) * ldb + bcol)
                         : (B + (size_t)brow * ldb + n0 + bcol);

    // prologue: tile 0 -> buffer 0
    {
        float4 av = *(const float4*)Ag;
        float4 bv = *(const float4*)Bg;
        As[0][acol + 0][arow] = av.x; As[0][acol + 1][arow] = av.y;
        As[0][acol + 2][arow] = av.z; As[0][acol + 3][arow] = av.w;
        if (BT) {
            Bs[0][bcol + 0][brow] = bv.x; Bs[0][bcol + 1][brow] = bv.y;
            Bs[0][bcol + 2][brow] = bv.z; Bs[0][bcol + 3][brow] = bv.w;
        } else {
            *(float4*)&Bs[0][brow][bcol] = bv;
        }
    }
    __syncthreads();

    int tm = (t >> 4) * 8, tn = (t & 15) * 8;
    float acc[8][8];
    #pragma unroll
    for (int i = 0; i < 8; i++)
        #pragma unroll
        for (int j = 0; j < 8; j++) acc[i][j] = 0.0f;

    int nk = K >> 3;
    for (int kt = 0; kt < nk; ++kt) {
        int buf = kt & 1;
        float4 an, bn;
        if (kt + 1 < nk) {
            an = *(const float4*)(Ag + (kt + 1) * 8);
            bn = BT ? *(const float4*)(Bg + (kt + 1) * 8)
                    : *(const float4*)(Bg + (size_t)(kt + 1) * 8 * ldb);
        }
        #pragma unroll
        for (int k = 0; k < 8; k++) {
            float a[8], b[8];
            *(float4*)&a[0] = *(const float4*)&As[buf][k][tm];
            *(float4*)&a[4] = *(const float4*)&As[buf][k][tm + 4];
            *(float4*)&b[0] = *(const float4*)&Bs[buf][k][tn];
            *(float4*)&b[4] = *(const float4*)&Bs[buf][k][tn + 4];
            #pragma unroll
            for (int i = 0; i < 8; i++)
                #pragma unroll
                for (int j = 0; j < 8; j++)
                    acc[i][j] = fmaf(a[i], b[j], acc[i][j]);
        }
        if (kt + 1 < nk) {
            int nb = buf ^ 1;
            As[nb][acol + 0][arow] = an.x; As[nb][acol + 1][arow] = an.y;
            As[nb][acol + 2][arow] = an.z; As[nb][acol + 3][arow] = an.w;
            if (BT) {
                Bs[nb][bcol + 0][brow] = bn.x; Bs[nb][bcol + 1][brow] = bn.y;
                Bs[nb][bcol + 2][brow] = bn.z; Bs[nb][bcol + 3][brow] = bn.w;
            } else {
                *(float4*)&Bs[nb][brow][bcol] = bn;
            }
        }
        __syncthreads();
    }

    float bq[8];
    if (BIAS) {
        #pragma unroll
        for (int j = 0; j < 8; j++) bq[j] = bias[n0 + tn + j];
    }
    #pragma unroll
    for (int i = 0; i < 8; i++) {
        float out[8];
        #pragma unroll
        for (int j = 0; j < 8; j++) {
            float v = alpha * acc[i][j];
            if (BIAS) v += bq[j];
            if (RELU) v = fmaxf(v, 0.0f);
            out[j] = v;
        }
        float* cp = C + (size_t)(m0 + tm + i) * ldc + n0 + tn;
        *(float4*)cp       = *(float4*)&out[0];
        *(float4*)(cp + 4) = *(float4*)&out[4];
    }
}

// ---------------- BatchNorm stats: per-channel mean / rsqrt(var+eps) ----------------
__global__ void bn_stats_k(const float* __restrict__ x, float* __restrict__ mu,
                           float* __restrict__ rv)
{
    __shared__ float red[32];
    int c = blockIdx.x;
    float s = 0.f, ss = 0.f;
    for (int r = threadIdx.x; r < ROWS; r += blockDim.x) {
        float v = x[(size_t)r * Ech + c];
        s += v; ss += v * v;
    }
    s  = blockReduce(s,  red, 0);
    ss = blockReduce(ss, red, 0);
    if (threadIdx.x == 0) {
        float m = s / (float)ROWS;
        float var = ss / (float)ROWS - m * m;
        mu[c] = m;
        rv[c] = rsqrtf(var + EPSV);
    }
}

// ---------------- BN apply + sinusoidal PE ----------------
__global__ void bn_pe_k(float* __restrict__ x, const float* __restrict__ mu,
                        const float* __restrict__ rv, const float* __restrict__ g,
                        const float* __restrict__ b)
{
    size_t idx = (size_t)blockIdx.x * blockDim.x + threadIdx.x;
    if (idx >= (size_t)ROWS * Ech) return;
    int c = (int)(idx & (Ech - 1));
    int row = (int)(idx >> 9);
    int s = row & (Ssz - 1);
    int i2 = c & ~1;
    float dt = expf(-logf(10000.0f) * (float)i2 / (float)Ech);
    float ang = (float)s * dt;
    float pe = (c & 1) ? cosf(ang) : sinf(ang);
    x[idx] = (x[idx] - mu[c]) * rv[c] * g[c] + b[c] + pe;
}

// ---------------- distance bias: exp(scale*(1 - d/rowmax)) ----------------
__global__ void distb_k(const float* __restrict__ dist, const float* __restrict__ scale_p,
                        float* __restrict__ out)
{
    __shared__ float red[32];
    size_t bq = blockIdx.x;
    const float* row = dist + bq * Ssz;
    float m = -INFINITY;
    for (int i = threadIdx.x; i < Ssz; i += blockDim.x) m = fmaxf(m, row[i]);
    m = blockReduce(m, red, 1);
    float sc = *scale_p;
    float invm = 1.0f / m;
    for (int i = threadIdx.x; i < Ssz; i += blockDim.x)
        out[bq * Ssz + i] = expf(sc * (1.0f - row[i] * invm));
}

// ---------------- per-row: softmax over 8 heads, average, * dist_bias, renorm ----------------
__global__ void softmax_avg_k(const float* __restrict__ scores,
                              const float* __restrict__ db,
                              float* __restrict__ wout)
{
    __shared__ float avg[1024];
    __shared__ float tmp[1024];
    __shared__ float red[32];
    int bq = blockIdx.x;
    int b = bq >> 10, q = bq & 1023;
    int t = threadIdx.x;

    for (int i = t; i < Ssz; i += blockDim.x) avg[i] = 0.0f;
    __syncthreads();

    for (int h = 0; h < Hh; h++) {
        const float* row = scores + (((size_t)(b * Hh + h) * Ssz + q) * Ssz);
        float m = -INFINITY;
        for (int i = t; i < Ssz; i += blockDim.x) m = fmaxf(m, row[i]);
        m = blockReduce(m, red, 1);
        float s = 0.0f;
        for (int i = t; i < Ssz; i += blockDim.x) {
            float e = expf(row[i] - m);
            tmp[i] = e;
            s += e;
        }
        s = blockReduce(s, red, 0);
        float inv = 1.0f / ((float)Hh * s);
        for (int i = t; i < Ssz; i += blockDim.x) avg[i] += tmp[i] * inv;
    }

    const float* dbr = db + (size_t)bq * Ssz;
    float s = 0.0f;
    for (int i = t; i < Ssz; i += blockDim.x) {
        float v = avg[i] * dbr[i];
        tmp[i] = v;
        s += v;
    }
    s = blockReduce(s, red, 0);
    float inv = 1.0f / s;
    for (int i = t; i < Ssz; i += blockDim.x)
        wout[(size_t)bq * Ssz + i] = tmp[i] * inv;
}

// ---------------- residual + LayerNorm (row = 512) ----------------
__global__ void add_ln_k(const float* __restrict__ xin, const float* __restrict__ res,
                         const float* __restrict__ g, const float* __restrict__ b,
                         float* __restrict__ xout)
{
    __shared__ float red[32];
    int row = blockIdx.x;
    int t = threadIdx.x;                       // 128 threads * 4 = 512
    const float4* x4 = (const float4*)(xin + (size_t)row * Ech);
    const float4* r4 = (const float4*)(res + (size_t)row * Ech);
    float4 a = x4[t], c = r4[t];
    float y0 = a.x + c.x, y1 = a.y + c.y, y2 = a.z + c.z, y3 = a.w + c.w;
    float s  = y0 + y1 + y2 + y3;
    float ss = y0 * y0 + y1 * y1 + y2 * y2 + y3 * y3;
    s  = blockReduce(s,  red, 0);
    ss = blockReduce(ss, red, 0);
    float mean = s / (float)Ech;
    float var  = ss / (float)Ech - mean * mean;
    float rstd = rsqrtf(var + EPSV);
    const float4* g4 = (const float4*)g;
    const float4* b4 = (const float4*)b;
    float4 gg = g4[t], bb = b4[t];
    float4 o;
    o.x = (y0 - mean) * rstd * gg.x + bb.x;
    o.y = (y1 - mean) * rstd * gg.y + bb.y;
    o.z = (y2 - mean) * rstd * gg.z + bb.z;
    o.w = (y3 - mean) * rstd * gg.w + bb.w;
    ((float4*)(xout + (size_t)row * Ech))[t] = o;
}

// ---------------- host orchestration ----------------
extern "C" void kernel_launch(void* const* d_in, const int* in_sizes, int n_in,
                              void* d_out, int out_size)
{
    const float* src        = (const float*)d_in[0];
    const float* distances  = (const float*)d_in[1];
    const float* proj_w     = (const float*)d_in[2];
    const float* proj_b     = (const float*)d_in[3];
    const float* bn_g       = (const float*)d_in[4];
    const float* bn_b       = (const float*)d_in[5];
    const float* in_proj_w  = (const float*)d_in[6];
    const float* in_proj_b  = (const float*)d_in[7];
    const float* dist_scale = (const float*)d_in[8];
    const float* lin1_w     = (const float*)d_in[9];
    const float* lin1_b     = (const float*)d_in[10];
    const float* lin2_w     = (const float*)d_in[11];
    const float* lin2_b     = (const float*)d_in[12];
    const float* n1_g       = (const float*)d_in[13];
    const float* n1_b       = (const float*)d_in[14];
    const float* n2_g       = (const float*)d_in[15];
    const float* n2_b       = (const float*)d_in[16];
    float* out = (float*)d_out;

    float *x, *qkv, *scores, *w, *db, *attn, *ff1, *ff2, *mu, *rv;
    cudaGetSymbolAddress((void**)&x,      g_x);
    cudaGetSymbolAddress((void**)&qkv,    g_qkv);
    cudaGetSymbolAddress((void**)&scores, g_scores);
    cudaGetSymbolAddress((void**)&w,      g_w);
    cudaGetSymbolAddress((void**)&db,     g_db);
    cudaGetSymbolAddress((void**)&attn,   g_attn);
    cudaGetSymbolAddress((void**)&ff1,    g_ff1);
    cudaGetSymbolAddress((void**)&ff2,    g_ff2);
    cudaGetSymbolAddress((void**)&mu,     g_mu);
    cudaGetSymbolAddress((void**)&rv,     g_rv);

    const long long SQKV = (long long)Ssz * 3 * Ech;     // 1572864
    const long long SHSS = (long long)Hh * Ssz * Ssz;    // 8388608
    const long long SSS  = (long long)Ssz * Ssz;         // 1048576
    const long long SXE  = (long long)Ssz * Ech;         // 524288

    // 1. input projection: x = src @ proj_w^T + proj_b
    gemm_k<true, false, true><<<dim3(Ech / 128, ROWS / 128, 1), 256>>>(
        src, proj_w, proj_b, x, ROWS, Ech, INd, INd, INd, Ech,
        1, 0, 0, 0, 0, 0, 0, 1.0f);

    // 2. BatchNorm stats + apply + PE
    bn_stats_k<<<Ech, 256>>>(x, mu, rv);
    bn_pe_k<<<(ROWS * Ech + 255) / 256, 256>>>(x, mu, rv, bn_g, bn_b);

    // 3. distance bias (layer-invariant)
    distb_k<<<ROWS, 256>>>(distances, dist_scale, db);

    const float scale = 0.125f;  // 1/sqrt(64)

    for (int l = 0; l < Ld; ++l) {
        // qkv = x @ in_proj_w^T + b
        gemm_k<true, false, true><<<dim3(3 * Ech / 128, ROWS / 128, 1), 256>>>(
            x, in_proj_w, in_proj_b, qkv, ROWS, 3 * Ech, Ech, Ech, Ech, 3 * Ech,
            1, 0, 0, 0, 0, 0, 0, 1.0f);

        // scores[b,h] = scale * q[b,h] @ k[b,h]^T   (64 batches)
        gemm_k<true, false, false><<<dim3(Ssz / 128, Ssz / 128, Bn * Hh), 256>>>(
            qkv, qkv + Ech, nullptr, scores, Ssz, Ssz, HDd,
            3 * Ech, 3 * Ech, Ssz,
            Hh, SQKV, HDd, SQKV, HDd, SHSS, SSS, scale);

        // per-row softmax over heads, average, *dist_bias, renormalize
        softmax_avg_k<<<ROWS, 256>>>(scores, db, w);

        // attn_out = w @ x   (8 batches)
        gemm_k<false, false, false><<<dim3(Ech / 128, Ssz / 128, Bn), 256>>>(
            w, x, nullptr, attn, Ssz, Ech, Ssz, Ssz, Ech, Ech,
            1, SSS, 0, SXE, 0, SXE, 0, 1.0f);

        // x = LN(x + attn_out)
        add_ln_k<<<ROWS, 128>>>(x, attn, n1_g, n1_b, x);

        // ff1 = relu(x @ lin1_w^T + b)
        gemm_k<true, true, true><<<dim3(FFd / 128, ROWS / 128, 1), 256>>>(
            x, lin1_w, lin1_b, ff1, ROWS, FFd, Ech, Ech, Ech, FFd,
            1, 0, 0, 0, 0, 0, 0, 1.0f);

        // ff2 = ff1 @ lin2_w^T + b
        gemm_k<true, false, true><<<dim3(Ech / 128, ROWS / 128, 1), 256>>>(
            ff1, lin2_w, lin2_b, ff2, ROWS, Ech, FFd, FFd, FFd, Ech,
            1, 0, 0, 0, 0, 0, 0, 1.0f);

        // x = LN(x + ff2); last layer writes final output
        add_ln_k<<<ROWS, 128>>>(x, ff2, n2_g, n2_b, (l == Ld - 1) ? out : x);
    }
}

// round 16
// speedup vs baseline: 3.4861x; 2.1597x over previous
#include <cuda_runtime.h>
#include <cuda_bf16.h>
#include <math.h>
#include <stdint.h>

typedef __nv_bfloat16 bf16;
static const int Ssz = 1024, Ech = 512, Hh = 8, ROWS = 8192;
#define EPSV 1e-5f

// ---------------- scratch ----------------
__device__ float g_x[8192 * 512];
__device__ bf16 g_xhi[8192 * 512], g_xlo[8192 * 512];
__device__ bf16 g_xThi[8 * 512 * 1024], g_xTlo[8 * 512 * 1024];
__device__ bf16 g_shi[8192 * 128], g_slo[8192 * 128];
__device__ bf16 g_pwhi[512 * 128], g_pwlo[512 * 128];
__device__ bf16 g_qwhi[1024 * 512], g_qwlo[1024 * 512];
__device__ bf16 g_l1hi[2048 * 512], g_l1lo[2048 * 512];
__device__ bf16 g_l2hi[512 * 2048], g_l2lo[512 * 2048];
__device__ bf16 g_qkhi[8192 * 1024], g_qklo[8192 * 1024];
__device__ float g_scores[67108864ull];
__device__ bf16 g_whi[8388608ull], g_wlo[8388608ull];
__device__ float g_db[8388608ull];
__device__ float g_attn[8192 * 512];
__device__ bf16 g_f1hi[8192 * 2048], g_f1lo[8192 * 2048];
__device__ float g_ff2[8192 * 512];
__device__ float g_mu[512], g_rv[512];

// ---------------- ptx helpers (all valid on base compute_103) ----------------
__device__ __forceinline__ uint32_t smem_u32(const void* p) {
    uint32_t a;
    asm("{ .reg .u64 t; cvta.to.shared.u64 t, %1; cvt.u32.u64 %0, t; }" : "=r"(a) : "l"(p));
    return a;
}
__device__ __forceinline__ void cpa16(uint32_t s, const void* g) {
    asm volatile("cp.async.cg.shared.global [%0], [%1], 16;" :: "r"(s), "l"(__cvta_generic_to_global(g)) : "memory");
}
#define LDSM4(r0, r1, r2, r3, a) \
    asm volatile("ldmatrix.sync.aligned.m8n8.x4.shared.b16 {%0,%1,%2,%3},[%4];" \
        : "=r"(r0), "=r"(r1), "=r"(r2), "=r"(r3) : "r"(a))
#define MMA16816(c, a, b) \
    asm volatile("mma.sync.aligned.m16n8k16.row.col.f32.bf16.bf16.f32 " \
        "{%0,%1,%2,%3},{%4,%5,%6,%7},{%8,%9},{%0,%1,%2,%3};" \
        : "+f"((c)[0]), "+f"((c)[1]), "+f"((c)[2]), "+f"((c)[3]) \
        : "r"((a)[0]), "r"((a)[1]), "r"((a)[2]), "r"((a)[3]), "r"((b)[0]), "r"((b)[1]))

// ---------------- mma.sync bf16-split NT GEMM: 128x128 tile, K-chunk 32 ----------------
// smem stage: Ahi(10240) Alo(10240) Bhi(10240) Blo(10240) = 40960 B; 2 stages.
// padded row stride 80 B (40 bf16) -> conflict-free ldmatrix.
static const int STGB = 40960, SMEMSZ = 2 * STGB;

template<bool BIAS, bool RELU, bool SPLIT>
__global__ __launch_bounds__(256, 2)
void mma_gemm(const bf16* __restrict__ Ahi, const bf16* __restrict__ Alo, int lda,
              const bf16* __restrict__ Bhi, const bf16* __restrict__ Blo, int ldb,
              const float* __restrict__ bias, float* __restrict__ C,
              bf16* __restrict__ Chi, bf16* __restrict__ Clo, int ldc,
              int nk, float alpha, int zdivH,
              long long aZb, long long aZh, long long bZb, long long bZh, long long cZ)
{
    extern __shared__ __align__(16) char smem[];
    uint32_t sb = smem_u32(smem);
    int t = threadIdx.x, wid = t >> 5, lane = t & 31;
    int z = blockIdx.z, bb = z / zdivH, hh = z - bb * zdivH;
    int m0 = blockIdx.y * 128, n0 = blockIdx.x * 128;
    const bf16* Ah = Ahi + bb * aZb + hh * aZh + (size_t)m0 * lda;
    const bf16* Al = Alo + bb * aZb + hh * aZh + (size_t)m0 * lda;
    const bf16* Bh = Bhi + bb * bZb + hh * bZh + (size_t)n0 * ldb;
    const bf16* Bl = Blo + bb * bZb + hh * bZh + (size_t)n0 * ldb;
    int warpM = (wid >> 1) * 32, warpN = (wid & 1) * 64;

    auto loadStage = [&](int s, int kt) {
        uint32_t base = sb + s * STGB;
        int k0 = kt * 32;
        #pragma unroll
        for (int u = 0; u < 2; u++) {
            int f = u * 256 + t;          // 0..511
            int r = f >> 2, c = f & 3;    // 128 rows x 4 chunks of 16B
            uint32_t so = r * 80 + c * 16;
            size_t ga = (size_t)r * lda + k0 + c * 8;
            size_t gb = (size_t)r * ldb + k0 + c * 8;
            cpa16(base + so,         Ah + ga);
            cpa16(base + 10240 + so, Al + ga);
            cpa16(base + 20480 + so, Bh + gb);
            cpa16(base + 30720 + so, Bl + gb);
        }
        asm volatile("cp.async.commit_group;" ::: "memory");
    };

    float acc[2][8][4];
    #pragma unroll
    for (int i = 0; i < 2; i++)
        #pragma unroll
        for (int j = 0; j < 8; j++)
            #pragma unroll
            for (int q = 0; q < 4; q++) acc[i][j][q] = 0.0f;

    int lrow = lane & 15, lseg = (lane >> 4) * 16;
    loadStage(0, 0);
    for (int kt = 0; kt < nk; kt++) {
        int s = kt & 1;
        asm volatile("cp.async.wait_group 0;" ::: "memory");
        __syncthreads();
        if (kt + 1 < nk) loadStage(s ^ 1, kt + 1);
        uint32_t base = sb + s * STGB;
        #pragma unroll
        for (int ks = 0; ks < 2; ks++) {
            uint32_t bh[8][2], bl[8][2];
            #pragma unroll
            for (int np = 0; np < 4; np++) {
                uint32_t r0, r1, r2, r3;
                uint32_t ad = base + 20480 + (warpN + np * 16 + lrow) * 80 + ks * 32 + lseg;
                LDSM4(r0, r1, r2, r3, ad);
                bh[np * 2][0] = r0; bh[np * 2][1] = r2;
                bh[np * 2 + 1][0] = r1; bh[np * 2 + 1][1] = r3;
                LDSM4(r0, r1, r2, r3, ad + 10240);
                bl[np * 2][0] = r0; bl[np * 2][1] = r2;
                bl[np * 2 + 1][0] = r1; bl[np * 2 + 1][1] = r3;
            }
            #pragma unroll
            for (int mi = 0; mi < 2; mi++) {
                uint32_t ah[4], al[4];
                uint32_t ad = base + (warpM + mi * 16 + lrow) * 80 + ks * 32 + lseg;
                LDSM4(ah[0], ah[1], ah[2], ah[3], ad);
                LDSM4(al[0], al[1], al[2], al[3], ad + 10240);
                #pragma unroll
                for (int nf = 0; nf < 8; nf++) {
                    MMA16816(acc[mi][nf], ah, bh[nf]);
                    MMA16816(acc[mi][nf], ah, bl[nf]);
                    MMA16816(acc[mi][nf], al, bh[nf]);
                }
            }
        }
    }

    // epilogue: c0,c1 -> (row, col..col+1); c2,c3 -> row+8
    int rBase = m0 + warpM + (lane >> 2);
    int cBase = n0 + warpN + (lane & 3) * 2;
    float* Cf = C + z * cZ;
    bf16* Ch = Chi + z * cZ;
    bf16* Cl = Clo + z * cZ;
    #pragma unroll
    for (int mi = 0; mi < 2; mi++)
        #pragma unroll
        for (int nf = 0; nf < 8; nf++) {
            int col = cBase + nf * 8;
            float b0 = 0.f, b1 = 0.f;
            if (BIAS) { b0 = bias[col]; b1 = bias[col + 1]; }
            #pragma unroll
            for (int hf = 0; hf < 2; hf++) {
                int row = rBase + mi * 16 + hf * 8;
                float v0 = alpha * acc[mi][nf][hf * 2] + b0;
                float v1 = alpha * acc[mi][nf][hf * 2 + 1] + b1;
                if (RELU) { v0 = fmaxf(v0, 0.f); v1 = fmaxf(v1, 0.f); }
                if (SPLIT) {
                    bf16 h0 = __float2bfloat16(v0), h1 = __float2bfloat16(v1);
                    bf16 l0 = __float2bfloat16(v0 - __bfloat162float(h0));
                    bf16 l1 = __float2bfloat16(v1 - __bfloat162float(h1));
                    bf16 hp[2] = {h0, h1}, lp[2] = {l0, l1};
                    *(uint32_t*)(Ch + (size_t)row * ldc + col) = *(uint32_t*)hp;
                    *(uint32_t*)(Cl + (size_t)row * ldc + col) = *(uint32_t*)lp;
                } else {
                    float2 o; o.x = v0; o.y = v1;
                    *(float2*)(Cf + (size_t)row * ldc + col) = o;
                }
            }
        }
}

// ---------------- reductions ----------------
__device__ __forceinline__ float blockReduce(float v, float* red, int isMax) {
    #pragma unroll
    for (int o = 16; o; o >>= 1) { float u = __shfl_xor_sync(~0u, v, o); v = isMax ? fmaxf(v, u) : v + u; }
    int lane = threadIdx.x & 31, wid = threadIdx.x >> 5, nw = blockDim.x >> 5;
    __syncthreads();
    if (lane == 0) red[wid] = v;
    __syncthreads();
    v = (threadIdx.x < nw) ? red[threadIdx.x] : (isMax ? -INFINITY : 0.0f);
    if (wid == 0) {
        #pragma unroll
        for (int o = 16; o; o >>= 1) { float u = __shfl_xor_sync(~0u, v, o); v = isMax ? fmaxf(v, u) : v + u; }
        if (lane == 0) red[0] = v;
    }
    __syncthreads();
    return red[0];
}

// ---------------- elementwise ----------------
__global__ void split_k(const float* __restrict__ in, bf16* __restrict__ h, bf16* __restrict__ l, int n) {
    int i = blockIdx.x * blockDim.x + threadIdx.x;
    if (i >= n) return;
    float v = in[i];
    bf16 hh = __float2bfloat16(v);
    h[i] = hh; l[i] = __float2bfloat16(v - __bfloat162float(hh));
}

__global__ void bn_stats_k(const float* __restrict__ x, float* __restrict__ mu, float* __restrict__ rv) {
    __shared__ float red[32];
    int c = blockIdx.x;
    float s = 0.f, ss = 0.f;
    for (int r = threadIdx.x; r < ROWS; r += blockDim.x) { float v = x[(size_t)r * Ech + c]; s += v; ss += v * v; }
    s = blockReduce(s, red, 0); ss = blockReduce(ss, red, 0);
    if (threadIdx.x == 0) { float m = s / ROWS; mu[c] = m; rv[c] = rsqrtf(ss / ROWS - m * m + EPSV); }
}

__global__ void bn_pe_k(float* __restrict__ x, const float* __restrict__ mu, const float* __restrict__ rv,
                        const float* __restrict__ g, const float* __restrict__ b,
                        bf16* __restrict__ xh, bf16* __restrict__ xl) {
    size_t i = (size_t)blockIdx.x * blockDim.x + threadIdx.x;
    if (i >= (size_t)ROWS * Ech) return;
    int c = (int)(i & 511), s = (int)(i >> 9) & 1023;
    float dt = expf(-logf(10000.0f) * (float)(c & ~1) / 512.0f);
    float ang = s * dt;
    float pe = (c & 1) ? cosf(ang) : sinf(ang);
    float v = (x[i] - mu[c]) * rv[c] * g[c] + b[c] + pe;
    x[i] = v;
    bf16 h = __float2bfloat16(v);
    xh[i] = h; xl[i] = __float2bfloat16(v - __bfloat162float(h));
}

__global__ void distb_k(const float* __restrict__ dist, const float* __restrict__ sp, float* __restrict__ out) {
    __shared__ float red[32];
    size_t bq = blockIdx.x;
    const float* row = dist + bq * Ssz;
    float m = -INFINITY;
    for (int i = threadIdx.x; i < Ssz; i += blockDim.x) m = fmaxf(m, row[i]);
    m = blockReduce(m, red, 1);
    float sc = *sp, im = 1.0f / m;
    for (int i = threadIdx.x; i < Ssz; i += blockDim.x) out[bq * Ssz + i] = expf(sc * (1.0f - row[i] * im));
}

__global__ void softmax_avg_k(const float* __restrict__ sc, const float* __restrict__ db,
                              bf16* __restrict__ wh, bf16* __restrict__ wl) {
    __shared__ float avg[1024], tmp[1024], red[32];
    int bq = blockIdx.x, b = bq >> 10, q = bq & 1023, t = threadIdx.x;
    for (int i = t; i < Ssz; i += blockDim.x) avg[i] = 0.0f;
    __syncthreads();
    for (int h = 0; h < Hh; h++) {
        const float* row = sc + ((size_t)(b * Hh + h) * Ssz + q) * Ssz;
        float m = -INFINITY;
        for (int i = t; i < Ssz; i += blockDim.x) m = fmaxf(m, row[i]);
        m = blockReduce(m, red, 1);
        float s = 0.0f;
        for (int i = t; i < Ssz; i += blockDim.x) { float e = expf(row[i] - m); tmp[i] = e; s += e; }
        s = blockReduce(s, red, 0);
        float inv = 1.0f / (8.0f * s);
        for (int i = t; i < Ssz; i += blockDim.x) avg[i] += tmp[i] * inv;
    }
    const float* dbr = db + (size_t)bq * Ssz;
    float s = 0.0f;
    for (int i = t; i < Ssz; i += blockDim.x) { float v = avg[i] * dbr[i]; tmp[i] = v; s += v; }
    s = blockReduce(s, red, 0);
    float inv = 1.0f / s;
    for (int i = t; i < Ssz; i += blockDim.x) {
        float v = tmp[i] * inv;
        bf16 h = __float2bfloat16(v);
        wh[(size_t)bq * Ssz + i] = h;
        wl[(size_t)bq * Ssz + i] = __float2bfloat16(v - __bfloat162float(h));
    }
}

__global__ void add_ln_k(const float* __restrict__ xin, const float* __restrict__ res,
                         const float* __restrict__ g, const float* __restrict__ b,
                         float* __restrict__ xout, bf16* __restrict__ xh, bf16* __restrict__ xl) {
    __shared__ float red[32];
    int row = blockIdx.x, t = threadIdx.x;
    float4 a = ((const float4*)(xin + (size_t)row * Ech))[t];
    float4 c = ((const float4*)(res + (size_t)row * Ech))[t];
    float y0 = a.x + c.x, y1 = a.y + c.y, y2 = a.z + c.z, y3 = a.w + c.w;
    float s = blockReduce(y0 + y1 + y2 + y3, red, 0);
    float ss = blockReduce(y0 * y0 + y1 * y1 + y2 * y2 + y3 * y3, red, 0);
    float mean = s / Ech, rstd = rsqrtf(ss / Ech - mean * mean + EPSV);
    float4 gg = ((const float4*)g)[t], bb = ((const float4*)b)[t];
    float4 o;
    o.x = (y0 - mean) * rstd * gg.x + bb.x; o.y = (y1 - mean) * rstd * gg.y + bb.y;
    o.z = (y2 - mean) * rstd * gg.z + bb.z; o.w = (y3 - mean) * rstd * gg.w + bb.w;
    ((float4*)(xout + (size_t)row * Ech))[t] = o;
    if (xh) {
        float vv[4] = {o.x, o.y, o.z, o.w};
        bf16 h[4], lo[4];
        #pragma unroll
        for (int q = 0; q < 4; q++) { h[q] = __float2bfloat16(vv[q]); lo[q] = __float2bfloat16(vv[q] - __bfloat162float(h[q])); }
        *(uint2*)(xh + (size_t)row * Ech + t * 4) = *(uint2*)h;
        *(uint2*)(xl + (size_t)row * Ech + t * 4) = *(uint2*)lo;
    }
}

__global__ void transpose_k(const float* __restrict__ x, bf16* __restrict__ th, bf16* __restrict__ tl) {
    __shared__ float tile[32][33];
    int b = blockIdx.z, s0 = blockIdx.x * 32, e0 = blockIdx.y * 32;
    int tx = threadIdx.x, ty = threadIdx.y;
    #pragma unroll
    for (int i = 0; i < 32; i += 8)
        tile[ty + i][tx] = x[((size_t)b * 1024 + s0 + ty + i) * 512 + e0 + tx];
    __syncthreads();
    #pragma unroll
    for (int i = 0; i < 32; i += 8) {
        float v = tile[tx][ty + i];
        size_t o = (size_t)b * 512 * 1024 + (size_t)(e0 + ty + i) * 1024 + s0 + tx;
        bf16 h = __float2bfloat16(v);
        th[o] = h; tl[o] = __float2bfloat16(v - __bfloat162float(h));
    }
}

// ---------------- host ----------------
extern "C" void kernel_launch(void* const* d_in, const int* in_sizes, int n_in, void* d_out, int out_size)
{
    const float* src = (const float*)d_in[0];
    const float* distances = (const float*)d_in[1];
    const float* proj_w = (const float*)d_in[2];
    const float* proj_b = (const float*)d_in[3];
    const float* bn_g = (const float*)d_in[4];
    const float* bn_b = (const float*)d_in[5];
    const float* in_proj_w = (const float*)d_in[6];
    const float* in_proj_b = (const float*)d_in[7];
    const float* dist_scale = (const float*)d_in[8];
    const float* lin1_w = (const float*)d_in[9];
    const float* lin1_b = (const float*)d_in[10];
    const float* lin2_w = (const float*)d_in[11];
    const float* lin2_b = (const float*)d_in[12];
    const float* n1_g = (const float*)d_in[13];
    const float* n1_b = (const float*)d_in[14];
    const float* n2_g = (const float*)d_in[15];
    const float* n2_b = (const float*)d_in[16];
    float* out = (float*)d_out;

    float *x, *scores, *db, *attn, *ff2, *mu, *rv;
    bf16 *xhi, *xlo, *xThi, *xTlo, *shi, *slo, *pwhi, *pwlo, *qwhi, *qwlo;
    bf16 *l1hi, *l1lo, *l2hi, *l2lo, *qkhi, *qklo, *whi, *wlo, *f1hi, *f1lo;
    cudaGetSymbolAddress((void**)&x, g_x);       cudaGetSymbolAddress((void**)&scores, g_scores);
    cudaGetSymbolAddress((void**)&db, g_db);     cudaGetSymbolAddress((void**)&attn, g_attn);
    cudaGetSymbolAddress((void**)&ff2, g_ff2);   cudaGetSymbolAddress((void**)&mu, g_mu);
    cudaGetSymbolAddress((void**)&rv, g_rv);
    cudaGetSymbolAddress((void**)&xhi, g_xhi);   cudaGetSymbolAddress((void**)&xlo, g_xlo);
    cudaGetSymbolAddress((void**)&xThi, g_xThi); cudaGetSymbolAddress((void**)&xTlo, g_xTlo);
    cudaGetSymbolAddress((void**)&shi, g_shi);   cudaGetSymbolAddress((void**)&slo, g_slo);
    cudaGetSymbolAddress((void**)&pwhi, g_pwhi); cudaGetSymbolAddress((void**)&pwlo, g_pwlo);
    cudaGetSymbolAddress((void**)&qwhi, g_qwhi); cudaGetSymbolAddress((void**)&qwlo, g_qwlo);
    cudaGetSymbolAddress((void**)&l1hi, g_l1hi); cudaGetSymbolAddress((void**)&l1lo, g_l1lo);
    cudaGetSymbolAddress((void**)&l2hi, g_l2hi); cudaGetSymbolAddress((void**)&l2lo, g_l2lo);
    cudaGetSymbolAddress((void**)&qkhi, g_qkhi); cudaGetSymbolAddress((void**)&qklo, g_qklo);
    cudaGetSymbolAddress((void**)&whi, g_whi);   cudaGetSymbolAddress((void**)&wlo, g_wlo);
    cudaGetSymbolAddress((void**)&f1hi, g_f1hi); cudaGetSymbolAddress((void**)&f1lo, g_f1lo);

    cudaFuncSetAttribute(mma_gemm<true, false, false>, cudaFuncAttributeMaxDynamicSharedMemorySize, SMEMSZ);
    cudaFuncSetAttribute(mma_gemm<true, false, true>,  cudaFuncAttributeMaxDynamicSharedMemorySize, SMEMSZ);
    cudaFuncSetAttribute(mma_gemm<false, false, false>, cudaFuncAttributeMaxDynamicSharedMemorySize, SMEMSZ);
    cudaFuncSetAttribute(mma_gemm<true, true, true>,   cudaFuncAttributeMaxDynamicSharedMemorySize, SMEMSZ);

    split_k<<<(8192 * 128 + 255) / 256, 256>>>(src, shi, slo, 8192 * 128);
    split_k<<<(512 * 128 + 255) / 256, 256>>>(proj_w, pwhi, pwlo, 512 * 128);
    split_k<<<(1024 * 512 + 255) / 256, 256>>>(in_proj_w, qwhi, qwlo, 1024 * 512);
    split_k<<<(2048 * 512 + 255) / 256, 256>>>(lin1_w, l1hi, l1lo, 2048 * 512);
    split_k<<<(512 * 2048 + 255) / 256, 256>>>(lin2_w, l2hi, l2lo, 512 * 2048);

    // proj: x = src @ proj_w^T + b   [8192,512] K=128
    mma_gemm<true, false, false><<<dim3(4, 64, 1), 256, SMEMSZ>>>(
        shi, slo, 128, pwhi, pwlo, 128, proj_b, x, (bf16*)0, (bf16*)0, 512, 4, 1.0f, 1, 0, 0, 0, 0, 0);
    bn_stats_k<<<Ech, 256>>>(x, mu, rv);
    bn_pe_k<<<(ROWS * Ech + 255) / 256, 256>>>(x, mu, rv, bn_g, bn_b, xhi, xlo);
    distb_k<<<ROWS, 256>>>(distances, dist_scale, db);

    const long long SSS = 1048576, SXE = 524288, SXT = 512 * 1024;
    for (int l = 0; l < 4; l++) {
        transpose_k<<<dim3(32, 16, 8), dim3(32, 8)>>>(x, xThi, xTlo);
        // qk = x @ in_proj_w[:1024]^T + b   [8192,1024] K=512 (v unused)
        mma_gemm<true, false, true><<<dim3(8, 64, 1), 256, SMEMSZ>>>(
            xhi, xlo, 512, qwhi, qwlo, 512, in_proj_b, (float*)0, qkhi, qklo, 1024, 16, 1.0f, 1, 0, 0, 0, 0, 0);
        // scores[b,h] = 0.125 * q @ k^T   [1024,1024] K=64, 64 batches
        mma_gemm<false, false, false><<<dim3(8, 8, 64), 256, SMEMSZ>>>(
            qkhi, qklo, 1024, qkhi + 512, qklo + 512, 1024, (float*)0, scores, (bf16*)0, (bf16*)0, 1024,
            2, 0.125f, 8, SSS, 64, SSS, 64, SSS);
        softmax_avg_k<<<ROWS, 256>>>(scores, db, whi, wlo);
        // attn = w @ x  (NT via xT)   [1024,512] K=1024, 8 batches
        mma_gemm<false, false, false><<<dim3(4, 8, 8), 256, SMEMSZ>>>(
            whi, wlo, 1024, xThi, xTlo, 1024, (float*)0, attn, (bf16*)0, (bf16*)0, 512,
            32, 1.0f, 1, SSS, 0, SXT, 0, SXE);
        add_ln_k<<<ROWS, 128>>>(x, attn, n1_g, n1_b, x, xhi, xlo);
        // ff1 = relu(x @ lin1_w^T + b)   [8192,2048] K=512
        mma_gemm<true, true, true><<<dim3(16, 64, 1), 256, SMEMSZ>>>(
            xhi, xlo, 512, l1hi, l1lo, 512, lin1_b, (float*)0, f1hi, f1lo, 2048, 16, 1.0f, 1, 0, 0, 0, 0, 0);
        // ff2 = ff1 @ lin2_w^T + b   [8192,512] K=2048
        mma_gemm<true, false, false><<<dim3(4, 64, 1), 256, SMEMSZ>>>(
            f1hi, f1lo, 2048, l2hi, l2lo, 2048, lin2_b, ff2, (bf16*)0, (bf16*)0, 512, 64, 1.0f, 1, 0, 0, 0, 0, 0);
        add_ln_k<<<ROWS, 128>>>(x, ff2, n2_g, n2_b, (l == 3) ? out : x,
                                (l == 3) ? (bf16*)0 : xhi, (l == 3) ? (bf16*)0 : xlo);
    }
}